// round 4
// baseline (speedup 1.0000x reference)
#include <cuda_runtime.h>
#include <math.h>

#define B_   2
#define S_   2048
#define D_   2048
#define H_   8
#define HD_  256
#define WIN_ 1024

// Scratch (no allocations allowed)
__device__ float g_q[B_*S_*H_*HD_];      // [B,S,H*HD] = QKV-proj Q output, RoPE'd in place
__device__ float g_k[B_*S_*HD_];         // [B,S,HD]
__device__ float g_v[B_*S_*HD_];
__device__ float g_attn[B_*S_*H_*HD_];   // attention output before O-proj

// ---------------------------------------------------------------------------
// SGEMM (NT): C[M,N] = A[M,K] * B[N,K]^T, all row-major, K contiguous.
// 128x128 block tile, BK=16, 256 threads, 8x8 micro-tile per thread with
// interleaved ownership (rows ti+16*i, cols ci+16*j) -> conflict-free LDS.
// ---------------------------------------------------------------------------
__global__ void __launch_bounds__(256) sgemm_nt(const float* __restrict__ A,
                                                const float* __restrict__ Bm,
                                                float* __restrict__ C,
                                                int M, int N, int K)
{
    __shared__ float As[16][128];
    __shared__ float Bs[16][128];
    int tid = threadIdx.x;
    int ti = tid >> 4, ci = tid & 15;
    int m0 = blockIdx.y << 7, n0 = blockIdx.x << 7;

    float acc[8][8];
    #pragma unroll
    for (int i = 0; i < 8; i++)
        #pragma unroll
        for (int j = 0; j < 8; j++) acc[i][j] = 0.f;

    for (int kt = 0; kt < K; kt += 16) {
        #pragma unroll
        for (int l = 0; l < 2; l++) {
            int idx = tid + (l << 8);          // 0..511 (float4 index)
            int row = idx >> 2;                // 0..127
            int kq  = (idx & 3) << 2;          // 0,4,8,12
            float4 va = *(const float4*)(A + (size_t)(m0 + row) * K + kt + kq);
            As[kq+0][row] = va.x; As[kq+1][row] = va.y;
            As[kq+2][row] = va.z; As[kq+3][row] = va.w;
            float4 vb = *(const float4*)(Bm + (size_t)(n0 + row) * K + kt + kq);
            Bs[kq+0][row] = vb.x; Bs[kq+1][row] = vb.y;
            Bs[kq+2][row] = vb.z; Bs[kq+3][row] = vb.w;
        }
        __syncthreads();
        #pragma unroll
        for (int k = 0; k < 16; k++) {
            float a[8], b[8];
            #pragma unroll
            for (int i = 0; i < 8; i++) a[i] = As[k][ti + (i << 4)];
            #pragma unroll
            for (int j = 0; j < 8; j++) b[j] = Bs[k][ci + (j << 4)];
            #pragma unroll
            for (int i = 0; i < 8; i++)
                #pragma unroll
                for (int j = 0; j < 8; j++) acc[i][j] += a[i] * b[j];
        }
        __syncthreads();
    }

    #pragma unroll
    for (int i = 0; i < 8; i++) {
        int row = m0 + ti + (i << 4);
        #pragma unroll
        for (int j = 0; j < 8; j++)
            C[(size_t)row * N + n0 + ci + (j << 4)] = acc[i][j];
    }
}

// ---------------------------------------------------------------------------
// RoPE applied in place to g_q (8 heads) and g_k (1 head).
// One block per (b,s), 128 threads (one per rotation pair).
// ---------------------------------------------------------------------------
__global__ void rope_kernel(const int* __restrict__ pos_ids)
{
    int bs = blockIdx.x;           // 0..B*S-1
    int i  = threadIdx.x;          // 0..127
    float pos  = (float)pos_ids[bs];
    float expo = (float)(2 * i) / (float)HD_;
    float inv  = powf(10000.0f, -expo);
    float ang  = pos * inv;
    float c = cosf(ang), s = sinf(ang);

    int qbase = bs * (H_ * HD_);
    #pragma unroll
    for (int h = 0; h < H_; h++) {
        float x1 = g_q[qbase + h*HD_ + i];
        float x2 = g_q[qbase + h*HD_ + 128 + i];
        g_q[qbase + h*HD_ + i]       = x1 * c - x2 * s;
        g_q[qbase + h*HD_ + 128 + i] = x2 * c + x1 * s;
    }
    int kbase = bs * HD_;
    float y1 = g_k[kbase + i], y2 = g_k[kbase + 128 + i];
    g_k[kbase + i]       = y1 * c - y2 * s;
    g_k[kbase + 128 + i] = y2 * c + y1 * s;
}

// ---------------------------------------------------------------------------
// Flash attention with sliding-window causal mask.
// Grid: (S/32, B*H). Block: 256 threads.
// Thread (r = tid>>3, sub = tid&7): query row r; score keys kk = sub+8*j;
// output dims d = sub + 8*dd (interleaved -> conflict-free V reads).
// smem rows padded to 257 floats (stride%32==1 -> conflict-free).
// ---------------------------------------------------------------------------
__global__ void __launch_bounds__(256) attn_kernel()
{
    extern __shared__ float sm[];
    float* Qs = sm;                 // 32 x 257
    float* Ks = sm + 32*257;        // 32 x 257
    float* Vs = sm + 2*32*257;      // 32 x 257
    float* Ps = sm + 3*32*257;      // 32 x 33

    int tid = threadIdx.x;
    int r = tid >> 3, sub = tid & 7;
    int bh = blockIdx.y;
    int b = bh >> 3, h = bh & 7;
    int q0 = blockIdx.x << 5;
    int q  = q0 + r;
    const float scale = 0.0625f;    // 1/sqrt(256)

    // Load + pre-scale Q tile
    for (int i = tid; i < 32 * HD_; i += 256) {
        int row = i >> 8, col = i & 255;
        Qs[row*257 + col] =
            g_q[((b*S_ + q0 + row) * H_ + h) * HD_ + col] * scale;
    }

    float acc[32];
    #pragma unroll
    for (int d = 0; d < 32; d++) acc[d] = 0.f;
    float m = -INFINITY, l = 0.f;

    int kbeg = q0 - (WIN_ - 1);
    if (kbeg < 0) kbeg = 0;
    kbeg &= ~31;

    for (int kt = kbeg; kt <= q0; kt += 32) {
        __syncthreads();   // all warps done with previous K/V tiles
        for (int i = tid; i < 32 * HD_; i += 256) {
            int row = i >> 8, col = i & 255;
            int gk = (b*S_ + kt + row) * HD_ + col;
            Ks[row*257 + col] = g_k[gk];
            Vs[row*257 + col] = g_v[gk];
        }
        __syncthreads();

        // ---- scores: this thread does keys kt + sub + 8*{0,1,2,3}
        float s0 = 0.f, s1 = 0.f, s2 = 0.f, s3 = 0.f;
        {
            const float* qrow = Qs + r*257;
            const float* k0 = Ks + (sub     ) * 257;
            const float* k1 = Ks + (sub +  8) * 257;
            const float* k2 = Ks + (sub + 16) * 257;
            const float* k3 = Ks + (sub + 24) * 257;
            #pragma unroll 8
            for (int d = 0; d < HD_; d++) {
                float qd = qrow[d];
                s0 += qd * k0[d];
                s1 += qd * k1[d];
                s2 += qd * k2[d];
                s3 += qd * k3[d];
            }
        }
        float sc[4] = {s0, s1, s2, s3};
        #pragma unroll
        for (int j = 0; j < 4; j++) {
            int k = kt + sub + (j << 3);
            bool valid = (k <= q) && (k > q - WIN_);
            if (!valid) sc[j] = -INFINITY;
        }

        // ---- online softmax (reduce across the 8 lanes of this row)
        float mt = fmaxf(fmaxf(sc[0], sc[1]), fmaxf(sc[2], sc[3]));
        mt = fmaxf(mt, __shfl_xor_sync(0xffffffffu, mt, 1));
        mt = fmaxf(mt, __shfl_xor_sync(0xffffffffu, mt, 2));
        mt = fmaxf(mt, __shfl_xor_sync(0xffffffffu, mt, 4));
        float mnew = fmaxf(m, mt);

        float alpha, p[4];
        if (mnew == -INFINITY) {    // tile fully masked for this row
            alpha = 1.f;
            p[0] = p[1] = p[2] = p[3] = 0.f;
        } else {
            alpha = __expf(m - mnew);            // m=-inf -> 0
            #pragma unroll
            for (int j = 0; j < 4; j++)
                p[j] = __expf(sc[j] - mnew);     // sc=-inf -> 0
        }
        float psum = p[0] + p[1] + p[2] + p[3];
        psum += __shfl_xor_sync(0xffffffffu, psum, 1);
        psum += __shfl_xor_sync(0xffffffffu, psum, 2);
        psum += __shfl_xor_sync(0xffffffffu, psum, 4);
        l = l * alpha + psum;
        m = mnew;

        #pragma unroll
        for (int d = 0; d < 32; d++) acc[d] *= alpha;

        Ps[r*33 + sub     ] = p[0];
        Ps[r*33 + sub +  8] = p[1];
        Ps[r*33 + sub + 16] = p[2];
        Ps[r*33 + sub + 24] = p[3];
        __syncwarp();   // Ps row written & read entirely within this warp

        // ---- P @ V : this thread owns output dims d = sub + 8*dd
        #pragma unroll 4
        for (int kk = 0; kk < 32; kk++) {
            float pk = Ps[r*33 + kk];
            const float* vr = Vs + kk*257 + sub;
            #pragma unroll
            for (int dd = 0; dd < 32; dd++)
                acc[dd] += pk * vr[dd << 3];
        }
    }

    float invl = 1.f / l;
    int obase = ((b*S_ + q) * H_ + h) * HD_ + sub;
    #pragma unroll
    for (int dd = 0; dd < 32; dd++)
        g_attn[obase + (dd << 3)] = acc[dd] * invl;
}

// ---------------------------------------------------------------------------
extern "C" void kernel_launch(void* const* d_in, const int* in_sizes, int n_in,
                              void* d_out, int out_size)
{
    (void)in_sizes; (void)n_in; (void)out_size;
    const float* hidden = (const float*)d_in[0];
    // d_in[1] = attention_mask (pure causal; reproduced analytically)
    const int*   pos    = (const int*)  d_in[2];
    const float* Wq     = (const float*)d_in[3];
    const float* Wk     = (const float*)d_in[4];
    const float* Wv     = (const float*)d_in[5];
    const float* Wo     = (const float*)d_in[6];
    float* out = (float*)d_out;

    float *q, *k, *v, *attn;
    cudaGetSymbolAddress((void**)&q,    g_q);
    cudaGetSymbolAddress((void**)&k,    g_k);
    cudaGetSymbolAddress((void**)&v,    g_v);
    cudaGetSymbolAddress((void**)&attn, g_attn);

    dim3 blk(256);
    // QKV projections
    sgemm_nt<<<dim3(16, 32), blk>>>(hidden, Wq, q, B_*S_, H_*HD_, D_);
    sgemm_nt<<<dim3( 2, 32), blk>>>(hidden, Wk, k, B_*S_, HD_,    D_);
    sgemm_nt<<<dim3( 2, 32), blk>>>(hidden, Wv, v, B_*S_, HD_,    D_);
    // RoPE in place
    rope_kernel<<<B_*S_, 128>>>(pos);
    // Attention
    size_t smem = (size_t)(3*32*257 + 32*33) * sizeof(float);
    cudaFuncSetAttribute(attn_kernel,
                         cudaFuncAttributeMaxDynamicSharedMemorySize, (int)smem);
    attn_kernel<<<dim3(S_/32, B_*H_), 256, smem>>>();
    // Output projection
    sgemm_nt<<<dim3(16, 32), blk>>>(attn, Wo, out, B_*S_, D_, H_*HD_);
}

// round 9
// speedup vs baseline: 4.9287x; 4.9287x over previous
#include <cuda_runtime.h>
#include <math.h>

#define B_   2
#define S_   2048
#define D_   2048
#define H_   8
#define HD_  256
#define WIN_ 1024
#define SCALE_ 0.0625f

// Scratch (no allocations allowed)
__device__ float g_q[B_*S_*H_*HD_];
__device__ float g_k[B_*S_*HD_];
__device__ float g_v[B_*S_*HD_];
__device__ float g_attn[B_*S_*H_*HD_];

// ---------------------------------------------------------------------------
// helpers
// ---------------------------------------------------------------------------
__device__ __forceinline__ unsigned cvt_tf32(float x) {
    unsigned u;
    asm("cvt.rna.tf32.f32 %0, %1;" : "=r"(u) : "f"(x));
    return u;
}
__device__ __forceinline__ float cvt_tf32f(float x) {
    return __uint_as_float(cvt_tf32(x));
}

__device__ __forceinline__ void mma_tf32(float c[4],
        unsigned a0, unsigned a1, unsigned a2, unsigned a3,
        unsigned b0, unsigned b1)
{
    asm volatile(
        "mma.sync.aligned.m16n8k8.row.col.f32.tf32.tf32.f32 "
        "{%0,%1,%2,%3}, {%4,%5,%6,%7}, {%8,%9}, {%0,%1,%2,%3};"
        : "+f"(c[0]), "+f"(c[1]), "+f"(c[2]), "+f"(c[3])
        : "r"(a0), "r"(a1), "r"(a2), "r"(a3), "r"(b0), "r"(b1));
}

__device__ __forceinline__ void cp_async16(float* smem_dst, const float* gsrc) {
    unsigned s = (unsigned)__cvta_generic_to_shared(smem_dst);
    asm volatile("cp.async.cg.shared.global [%0], [%1], 16;" :: "r"(s), "l"(gsrc));
}

// ---------------------------------------------------------------------------
// tf32 GEMM (NT): C[M,N] = A[M,K] * B[N,K]^T, row-major, K contiguous,
// all dims multiples of 128 (K multiple of 32).
// BM=BN=128, BK=32, 128 threads (4 warps, 2x2), warp tile 64x64.
// smem stride 36 (== 4 mod 32): conflict-free fragment LDS (bank = 4g+ln).
// cp.async double-buffered. tf32 rounding (RNA) at fragment load.
// ---------------------------------------------------------------------------
#define GSTR 36

__device__ __forceinline__ void gemm_body(const float* __restrict__ A,
                                          const float* __restrict__ Bm,
                                          float* __restrict__ C,
                                          int N, int K, int m0, int n0,
                                          float* dsm)
{
    float* As = dsm;                    // [2][128*GSTR]
    float* Bs = dsm + 2*128*GSTR;       // [2][128*GSTR]

    int tid = threadIdx.x;
    int w = tid >> 5, L = tid & 31;
    int wm = (w >> 1) << 6, wn = (w & 1) << 6;
    int g = L >> 2, ln = L & 3;

    float acc[4][8][4];
    #pragma unroll
    for (int i = 0; i < 4; i++)
        #pragma unroll
        for (int j = 0; j < 8; j++)
            #pragma unroll
            for (int v = 0; v < 4; v++) acc[i][j][v] = 0.f;

    int nk = K >> 5;

    // prologue: tile 0 -> stage 0
    #pragma unroll
    for (int t8 = 0; t8 < 8; t8++) {
        int idx = tid + (t8 << 7);
        int row = idx >> 3, j = (idx & 7) << 2;
        cp_async16(&As[row*GSTR + j], A  + (size_t)(m0 + row) * K + j);
        cp_async16(&Bs[row*GSTR + j], Bm + (size_t)(n0 + row) * K + j);
    }
    asm volatile("cp.async.commit_group;");

    for (int t = 0; t < nk; t++) {
        int s = t & 1;
        if (t + 1 < nk) {
            int kt = (t + 1) << 5;
            float* Ad = As + (s ^ 1) * 128*GSTR;
            float* Bd = Bs + (s ^ 1) * 128*GSTR;
            #pragma unroll
            for (int t8 = 0; t8 < 8; t8++) {
                int idx = tid + (t8 << 7);
                int row = idx >> 3, j = (idx & 7) << 2;
                cp_async16(&Ad[row*GSTR + j], A  + (size_t)(m0 + row) * K + kt + j);
                cp_async16(&Bd[row*GSTR + j], Bm + (size_t)(n0 + row) * K + kt + j);
            }
        }
        asm volatile("cp.async.commit_group;");
        asm volatile("cp.async.wait_group 1;");
        __syncthreads();

        const float* Ab = As + s * 128*GSTR;
        const float* Bb = Bs + s * 128*GSTR;
        #pragma unroll
        for (int ks = 0; ks < 4; ks++) {
            unsigned a[4][4];
            #pragma unroll
            for (int mf = 0; mf < 4; mf++) {
                const float* Ar = Ab + (wm + (mf << 4) + g) * GSTR + (ks << 3);
                a[mf][0] = cvt_tf32(Ar[ln]);
                a[mf][1] = cvt_tf32(Ar[8*GSTR + ln]);
                a[mf][2] = cvt_tf32(Ar[ln + 4]);
                a[mf][3] = cvt_tf32(Ar[8*GSTR + ln + 4]);
            }
            #pragma unroll
            for (int nf = 0; nf < 8; nf++) {
                const float* Br = Bb + (wn + (nf << 3) + g) * GSTR + (ks << 3);
                unsigned b0 = cvt_tf32(Br[ln]);
                unsigned b1 = cvt_tf32(Br[ln + 4]);
                #pragma unroll
                for (int mf = 0; mf < 4; mf++)
                    mma_tf32(acc[mf][nf], a[mf][0], a[mf][1], a[mf][2], a[mf][3], b0, b1);
            }
        }
        __syncthreads();
    }

    // epilogue: c0,c1 -> (row, 2ln..2ln+1); c2,c3 -> (row+8, ...)
    #pragma unroll
    for (int mf = 0; mf < 4; mf++) {
        size_t row = (size_t)(m0 + wm + (mf << 4) + g);
        #pragma unroll
        for (int nf = 0; nf < 8; nf++) {
            size_t col = (size_t)(n0 + wn + (nf << 3) + (ln << 1));
            *(float2*)&C[row * N + col]       = make_float2(acc[mf][nf][0], acc[mf][nf][1]);
            *(float2*)&C[(row + 8) * N + col] = make_float2(acc[mf][nf][2], acc[mf][nf][3]);
        }
    }
}

__global__ void __launch_bounds__(128, 2) gemm_k(const float* __restrict__ A,
        const float* __restrict__ Bm, float* __restrict__ C, int N, int K)
{
    extern __shared__ float dsm[];
    gemm_body(A, Bm, C, N, K, blockIdx.y << 7, blockIdx.x << 7, dsm);
}

// merged K+V projection (N=256 each): blockIdx.x 0..3
__global__ void __launch_bounds__(128, 2) gemm_kv(const float* __restrict__ A,
        const float* __restrict__ Bk, const float* __restrict__ Bv,
        float* __restrict__ Ck, float* __restrict__ Cv, int K)
{
    extern __shared__ float dsm[];
    int x = blockIdx.x;
    if (x < 2) gemm_body(A, Bk, Ck, 256, K, blockIdx.y << 7, x << 7, dsm);
    else       gemm_body(A, Bv, Cv, 256, K, blockIdx.y << 7, (x - 2) << 7, dsm);
}

// ---------------------------------------------------------------------------
// RoPE in place: g_q (8 heads) and g_k (1 head). One block per (b,s).
// ---------------------------------------------------------------------------
__global__ void rope_kernel(const int* __restrict__ pos_ids)
{
    int bs = blockIdx.x;
    int i  = threadIdx.x;          // 0..127
    float pos  = (float)pos_ids[bs];
    float expo = (float)(2 * i) / (float)HD_;
    float inv  = powf(10000.0f, -expo);
    float ang  = pos * inv;
    float c = cosf(ang), s = sinf(ang);

    int qbase = bs * (H_ * HD_);
    #pragma unroll
    for (int h = 0; h < H_; h++) {
        float x1 = g_q[qbase + h*HD_ + i];
        float x2 = g_q[qbase + h*HD_ + 128 + i];
        g_q[qbase + h*HD_ + i]       = x1 * c - x2 * s;
        g_q[qbase + h*HD_ + 128 + i] = x2 * c + x1 * s;
    }
    int kbase = bs * HD_;
    float y1 = g_k[kbase + i], y2 = g_k[kbase + 128 + i];
    g_k[kbase + i]       = y1 * c - y2 * s;
    g_k[kbase + 128 + i] = y2 * c + y1 * s;
}

// ---------------------------------------------------------------------------
// Flash attention (tf32 mma), sliding-window causal.
// Grid: (S/64, B*H). 256 threads = 8 warps: qw = w&3 (16 q-rows each),
// dg = w>>2 (d-half of 256 for PV). Both d-groups compute S redundantly;
// dg0 writes P (tf32) to smem; all warps read P fragments for PV.
// Strides: Q/K 260, P 68 (==4 mod 32, loads indexed by g -> bank 4g+ln),
// V 264 (==8 mod 32, loads indexed by ln -> bank 8ln+g). All conflict-free.
// ---------------------------------------------------------------------------
#define QSTR 260
#define KSTR 260
#define VSTR 264
#define PSTR 68
#define ATTN_SMEM ((64*QSTR + 64*KSTR + 64*VSTR + 64*PSTR) * 4)

__global__ void __launch_bounds__(256, 1) attn_mma()
{
    extern __shared__ float sm[];
    float* Qs = sm;
    float* Ks = Qs + 64*QSTR;
    float* Vs = Ks + 64*KSTR;
    float* Ps = Vs + 64*VSTR;

    int tid = threadIdx.x;
    int w = tid >> 5, L = tid & 31;
    int qw = w & 3, dg = w >> 2;
    int g = L >> 2, ln = L & 3;
    int bh = blockIdx.y;
    int b = bh >> 3, h = bh & 7;
    int q0 = blockIdx.x << 6;
    int dbase = dg << 7;

    // ---- fill Q (scale + tf32 round)
    for (int m = tid; m < 64*64; m += 256) {
        int row = m >> 6, c4 = (m & 63) << 2;
        const float4 v = *(const float4*)&g_q[((size_t)(b*S_ + q0 + row) * H_ + h) * HD_ + c4];
        float4 o;
        o.x = cvt_tf32f(v.x * SCALE_);
        o.y = cvt_tf32f(v.y * SCALE_);
        o.z = cvt_tf32f(v.z * SCALE_);
        o.w = cvt_tf32f(v.w * SCALE_);
        *(float4*)&Qs[row*QSTR + c4] = o;
    }

    float oacc[16][4];
    #pragma unroll
    for (int i = 0; i < 16; i++)
        #pragma unroll
        for (int v = 0; v < 4; v++) oacc[i][v] = 0.f;

    float ml = -INFINITY, mh = -INFINITY, ll = 0.f, lh = 0.f;
    int qlo = q0 + (qw << 4) + g;
    int qhi = qlo + 8;

    int kbeg = q0 - (WIN_ - 1);
    if (kbeg < 0) kbeg = 0;
    kbeg &= ~63;

    for (int kt = kbeg; kt <= q0; kt += 64) {
        __syncthreads();   // prior tile's K/V/P reads done
        // ---- fill K, V (tf32 round)
        for (int m = tid; m < 64*64; m += 256) {
            int row = m >> 6, c4 = (m & 63) << 2;
            size_t gi = (size_t)(b*S_ + kt + row) * HD_ + c4;
            float4 kv = *(const float4*)&g_k[gi];
            float4 ko;
            ko.x = cvt_tf32f(kv.x); ko.y = cvt_tf32f(kv.y);
            ko.z = cvt_tf32f(kv.z); ko.w = cvt_tf32f(kv.w);
            *(float4*)&Ks[row*KSTR + c4] = ko;
            float4 vv = *(const float4*)&g_v[gi];
            float4 vo;
            vo.x = cvt_tf32f(vv.x); vo.y = cvt_tf32f(vv.y);
            vo.z = cvt_tf32f(vv.z); vo.w = cvt_tf32f(vv.w);
            *(float4*)&Vs[row*VSTR + c4] = vo;
        }
        __syncthreads();

        // ---- S = Q K^T (16 x 64 per warp, full d=256 contraction)
        float sacc[8][4];
        #pragma unroll
        for (int i = 0; i < 8; i++)
            #pragma unroll
            for (int v = 0; v < 4; v++) sacc[i][v] = 0.f;

        const float* Qb = Qs + ((qw << 4) + g) * QSTR;
        #pragma unroll 8
        for (int ks = 0; ks < 32; ks++) {
            int kk = ks << 3;
            unsigned a0 = __float_as_uint(Qb[kk + ln]);
            unsigned a1 = __float_as_uint(Qb[8*QSTR + kk + ln]);
            unsigned a2 = __float_as_uint(Qb[kk + ln + 4]);
            unsigned a3 = __float_as_uint(Qb[8*QSTR + kk + ln + 4]);
            #pragma unroll
            for (int nf = 0; nf < 8; nf++) {
                const float* Kb = Ks + ((nf << 3) + g) * KSTR + kk;
                unsigned b0 = __float_as_uint(Kb[ln]);
                unsigned b1 = __float_as_uint(Kb[ln + 4]);
                mma_tf32(sacc[nf], a0, a1, a2, a3, b0, b1);
            }
        }

        // ---- mask: cols kt+nf*8+2ln(+1); rows qlo (c0,c1) / qhi (c2,c3)
        #pragma unroll
        for (int nf = 0; nf < 8; nf++) {
            int c0 = kt + (nf << 3) + (ln << 1);
            int c1 = c0 + 1;
            if (c0 > qlo || c0 <= qlo - WIN_) sacc[nf][0] = -INFINITY;
            if (c1 > qlo || c1 <= qlo - WIN_) sacc[nf][1] = -INFINITY;
            if (c0 > qhi || c0 <= qhi - WIN_) sacc[nf][2] = -INFINITY;
            if (c1 > qhi || c1 <= qhi - WIN_) sacc[nf][3] = -INFINITY;
        }

        // ---- online softmax (rows qlo / qhi; lane group = 4 lanes same g)
        float mtl = -INFINITY, mth = -INFINITY;
        #pragma unroll
        for (int nf = 0; nf < 8; nf++) {
            mtl = fmaxf(mtl, fmaxf(sacc[nf][0], sacc[nf][1]));
            mth = fmaxf(mth, fmaxf(sacc[nf][2], sacc[nf][3]));
        }
        mtl = fmaxf(mtl, __shfl_xor_sync(0xffffffffu, mtl, 1));
        mtl = fmaxf(mtl, __shfl_xor_sync(0xffffffffu, mtl, 2));
        mth = fmaxf(mth, __shfl_xor_sync(0xffffffffu, mth, 1));
        mth = fmaxf(mth, __shfl_xor_sync(0xffffffffu, mth, 2));

        float mnl = fmaxf(ml, mtl), mnh = fmaxf(mh, mth);
        float al = (mnl == -INFINITY) ? 1.f : __expf(ml - mnl);
        float ah = (mnh == -INFINITY) ? 1.f : __expf(mh - mnh);

        float p[8][4];
        float rsl = 0.f, rsh = 0.f;
        #pragma unroll
        for (int nf = 0; nf < 8; nf++) {
            p[nf][0] = (mnl > -INFINITY) ? __expf(sacc[nf][0] - mnl) : 0.f;
            p[nf][1] = (mnl > -INFINITY) ? __expf(sacc[nf][1] - mnl) : 0.f;
            p[nf][2] = (mnh > -INFINITY) ? __expf(sacc[nf][2] - mnh) : 0.f;
            p[nf][3] = (mnh > -INFINITY) ? __expf(sacc[nf][3] - mnh) : 0.f;
            rsl += p[nf][0] + p[nf][1];
            rsh += p[nf][2] + p[nf][3];
        }
        rsl += __shfl_xor_sync(0xffffffffu, rsl, 1);
        rsl += __shfl_xor_sync(0xffffffffu, rsl, 2);
        rsh += __shfl_xor_sync(0xffffffffu, rsh, 1);
        rsh += __shfl_xor_sync(0xffffffffu, rsh, 2);
        ll = ll * al + rsl;
        lh = lh * ah + rsh;
        ml = mnl; mh = mnh;

        #pragma unroll
        for (int nf = 0; nf < 16; nf++) {
            oacc[nf][0] *= al; oacc[nf][1] *= al;
            oacc[nf][2] *= ah; oacc[nf][3] *= ah;
        }

        // ---- dg0 writes P (tf32) to smem
        if (dg == 0) {
            float* Pb = Ps + ((qw << 4) + g) * PSTR;
            #pragma unroll
            for (int nf = 0; nf < 8; nf++) {
                int c = (nf << 3) + (ln << 1);
                *(float2*)&Pb[c] =
                    make_float2(cvt_tf32f(p[nf][0]), cvt_tf32f(p[nf][1]));
                *(float2*)&Pb[8*PSTR + c] =
                    make_float2(cvt_tf32f(p[nf][2]), cvt_tf32f(p[nf][3]));
            }
        }
        __syncthreads();

        // ---- O += P @ V (this warp's d-half: 128 cols)
        const float* Pb = Ps + ((qw << 4) + g) * PSTR;
        #pragma unroll
        for (int ks = 0; ks < 8; ks++) {
            int kk = ks << 3;
            unsigned a0 = __float_as_uint(Pb[kk + ln]);
            unsigned a1 = __float_as_uint(Pb[8*PSTR + kk + ln]);
            unsigned a2 = __float_as_uint(Pb[kk + ln + 4]);
            unsigned a3 = __float_as_uint(Pb[8*PSTR + kk + ln + 4]);
            const float* V0 = Vs + (kk + ln) * VSTR + dbase + g;
            const float* V1 = Vs + (kk + ln + 4) * VSTR + dbase + g;
            #pragma unroll
            for (int nf = 0; nf < 16; nf++) {
                unsigned b0 = __float_as_uint(V0[nf << 3]);
                unsigned b1 = __float_as_uint(V1[nf << 3]);
                mma_tf32(oacc[nf], a0, a1, a2, a3, b0, b1);
            }
        }
    }

    // ---- epilogue: normalize and store
    float il = 1.f / ll, ih = 1.f / lh;
    size_t rlo = ((size_t)(b*S_ + qlo) * H_ + h) * HD_;
    size_t rhi = ((size_t)(b*S_ + qhi) * H_ + h) * HD_;
    #pragma unroll
    for (int nf = 0; nf < 16; nf++) {
        int c = dbase + (nf << 3) + (ln << 1);
        *(float2*)&g_attn[rlo + c] = make_float2(oacc[nf][0] * il, oacc[nf][1] * il);
        *(float2*)&g_attn[rhi + c] = make_float2(oacc[nf][2] * ih, oacc[nf][3] * ih);
    }
}

// ---------------------------------------------------------------------------
extern "C" void kernel_launch(void* const* d_in, const int* in_sizes, int n_in,
                              void* d_out, int out_size)
{
    (void)in_sizes; (void)n_in; (void)out_size;
    const float* hidden = (const float*)d_in[0];
    // d_in[1] = attention_mask (pure causal; reproduced analytically)
    const int*   pos    = (const int*)  d_in[2];
    const float* Wq     = (const float*)d_in[3];
    const float* Wk     = (const float*)d_in[4];
    const float* Wv     = (const float*)d_in[5];
    const float* Wo     = (const float*)d_in[6];
    float* out = (float*)d_out;

    float *q, *k, *v, *attn;
    cudaGetSymbolAddress((void**)&q,    g_q);
    cudaGetSymbolAddress((void**)&k,    g_k);
    cudaGetSymbolAddress((void**)&v,    g_v);
    cudaGetSymbolAddress((void**)&attn, g_attn);

    const int gemm_smem = 2*2*128*GSTR*4;   // 73728
    cudaFuncSetAttribute(gemm_k,  cudaFuncAttributeMaxDynamicSharedMemorySize, gemm_smem);
    cudaFuncSetAttribute(gemm_kv, cudaFuncAttributeMaxDynamicSharedMemorySize, gemm_smem);
    cudaFuncSetAttribute(attn_mma, cudaFuncAttributeMaxDynamicSharedMemorySize, ATTN_SMEM);

    // Q projection: [4096,2048] = hidden @ Wq^T
    gemm_k<<<dim3(16, 32), 128, gemm_smem>>>(hidden, Wq, q, H_*HD_, D_);
    // K and V projections merged: [4096,256] each
    gemm_kv<<<dim3(4, 32), 128, gemm_smem>>>(hidden, Wk, Wv, k, v, D_);
    // RoPE in place
    rope_kernel<<<B_*S_, 128>>>(pos);
    // Attention
    attn_mma<<<dim3(S_/64, B_*H_), 256, ATTN_SMEM>>>();
    // Output projection: out = attn @ Wo^T
    gemm_k<<<dim3(16, 32), 128, gemm_smem>>>(attn, Wo, out, D_, H_*HD_);
}